// round 15
// baseline (speedup 1.0000x reference)
#include <cuda_runtime.h>
#include <cuda_bf16.h>
#include <cstdint>

#define BB   64
#define TT   512
#define II   256
#define HH   1024
#define G4   4096
#define HOR  24
#define NCTA 128

typedef unsigned long long u64;
typedef uint32_t u32;
typedef uint16_t u16;

// ---- scratch (device globals; allocation-free) ----
__device__ float g_xg[(size_t)TT * G4 * BB];           // [T][4H][B]
__device__ float g_h2[HH * BB];                        // layer1 final h [jb][b]
__device__ __nv_bfloat16 g_hhi[2][(size_t)BB * HH];    // ping-pong split h, [b][k]
__device__ __nv_bfloat16 g_hlo[2][(size_t)BB * HH];
__device__ __nv_bfloat16 g_h1hi[(size_t)TT * BB * HH]; // layer0 h history split hi, [t][b][k]
__device__ __nv_bfloat16 g_h1lo[(size_t)TT * BB * HH]; // layer0 h history split lo
__device__ int g_bar[TT];

// ---- scalar helpers ----
__device__ __forceinline__ u64 pack2(float lo, float hi) {
    u64 r; asm("mov.b64 %0, {%1, %2};" : "=l"(r) : "f"(lo), "f"(hi)); return r;
}
__device__ __forceinline__ void fma2(u64& d, u64 a, u64 b) {
    asm("fma.rn.f32x2 %0, %1, %2, %0;" : "+l"(d) : "l"(a), "l"(b));
}
__device__ __forceinline__ float sigm(float x) { return 1.0f / (1.0f + __expf(-x)); }

// m16n8k16 bf16 mma, accumulate in place
__device__ __forceinline__ void mma16816(float* d, const u32* a, const u32* b) {
    asm volatile(
        "mma.sync.aligned.m16n8k16.row.col.f32.bf16.bf16.f32 "
        "{%0,%1,%2,%3}, {%4,%5,%6,%7}, {%8,%9}, {%0,%1,%2,%3};\n"
        : "+f"(d[0]), "+f"(d[1]), "+f"(d[2]), "+f"(d[3])
        : "r"(a[0]), "r"(a[1]), "r"(a[2]), "r"(a[3]), "r"(b[0]), "r"(b[1]));
}

// ---- cp.async helpers ----
#define CP_ASYNC16(dst_u32, src_ptr) \
    asm volatile("cp.async.cg.shared.global [%0], [%1], 16;" \
        :: "r"(dst_u32), "l"(src_ptr) : "memory")
#define CP_COMMIT() asm volatile("cp.async.commit_group;" ::: "memory")
#define CP_WAIT0()  asm volatile("cp.async.wait_group 0;" ::: "memory")

// ---- zero barrier counters ----
__global__ void zero_state() {
    int i = blockIdx.x * blockDim.x + threadIdx.x;
    if (i < TT) g_bar[i] = 0;
}

// ---- layer-0 input projection GEMM (fp32 FFMA2, proven; K=II) ----
__global__ __launch_bounds__(128) void gemm0(
    const float* __restrict__ X, const float* __restrict__ W,
    const float* __restrict__ bih, const float* __restrict__ bhh)
{
    __shared__ __align__(16) float sA[16 * 68];
    __shared__ __align__(16) float sWt[16 * 132];
    __shared__ float sBias[128];

    const int tid = threadIdx.x;
    const int t   = blockIdx.y;
    const int j0  = blockIdx.x * 128;
    const int jg  = tid & 15;
    const int bg  = tid >> 4;

    sBias[tid] = bih[j0 + tid] + bhh[j0 + tid];
    __syncthreads();

    u64 acc[32];
    #pragma unroll
    for (int jl = 0; jl < 8; jl++) {
        float bj = sBias[jg * 8 + jl];
        u64 p = pack2(bj, bj);
        acc[jl * 4 + 0] = p; acc[jl * 4 + 1] = p;
        acc[jl * 4 + 2] = p; acc[jl * 4 + 3] = p;
    }

    for (int k0 = 0; k0 < II; k0 += 16) {
        __syncthreads();
        #pragma unroll
        for (int q = 0; q < 2; q++) {
            int f = q * 128 + tid;
            int b = f >> 2, kq = f & 3;
            float4 v = *(const float4*)(X + ((size_t)b * TT + t) * II + k0 + kq * 4);
            sA[(kq * 4 + 0) * 68 + b] = v.x;
            sA[(kq * 4 + 1) * 68 + b] = v.y;
            sA[(kq * 4 + 2) * 68 + b] = v.z;
            sA[(kq * 4 + 3) * 68 + b] = v.w;
        }
        #pragma unroll
        for (int q = 0; q < 4; q++) {
            int f = q * 128 + tid;
            int j = f >> 2, kq = f & 3;
            float4 v = *(const float4*)(W + (size_t)(j0 + j) * II + k0 + kq * 4);
            sWt[(kq * 4 + 0) * 132 + j] = v.x;
            sWt[(kq * 4 + 1) * 132 + j] = v.y;
            sWt[(kq * 4 + 2) * 132 + j] = v.z;
            sWt[(kq * 4 + 3) * 132 + j] = v.w;
        }
        __syncthreads();
        #pragma unroll
        for (int kk = 0; kk < 16; kk++) {
            longlong2 ha = *(const longlong2*)(sA + kk * 68 + bg * 8);
            longlong2 hb = *(const longlong2*)(sA + kk * 68 + bg * 8 + 4);
            float4 w0 = *(const float4*)(sWt + kk * 132 + jg * 8);
            float4 w1 = *(const float4*)(sWt + kk * 132 + jg * 8 + 4);
            u64 hq[4] = { (u64)ha.x, (u64)ha.y, (u64)hb.x, (u64)hb.y };
            u64 p[8]  = { pack2(w0.x, w0.x), pack2(w0.y, w0.y),
                          pack2(w0.z, w0.z), pack2(w0.w, w0.w),
                          pack2(w1.x, w1.x), pack2(w1.y, w1.y),
                          pack2(w1.z, w1.z), pack2(w1.w, w1.w) };
            #pragma unroll
            for (int jl = 0; jl < 8; jl++)
                #pragma unroll
                for (int bp = 0; bp < 4; bp++)
                    fma2(acc[jl * 4 + bp], hq[bp], p[jl]);
        }
    }
    #pragma unroll
    for (int jl = 0; jl < 8; jl++) {
        float* orow = g_xg + ((size_t)t * G4 + j0 + jg * 8 + jl) * BB + bg * 8;
        *(u64*)(orow + 0) = acc[jl * 4 + 0];
        *(u64*)(orow + 2) = acc[jl * 4 + 1];
        *(u64*)(orow + 4) = acc[jl * 4 + 2];
        *(u64*)(orow + 6) = acc[jl * 4 + 3];
    }
}

// ---- smem layout shared by recurrence + xg1 kernels ----
#define WPIT   1032
#define HPIT   136
#define SM_WHI 0
#define SM_WLO (32 * WPIT * 2)                 // 66048
#define SM_H   (SM_WLO + 32 * WPIT * 2)        // 132096
#define HPLANE (64 * HPIT * 2)                 // 17408
#define SM_XG  (SM_H + 4 * HPLANE)             // 201728; 32x68 f32 = 8704
#define SMEM_TC (SM_XG + 32 * 68 * 4)          // 210432

// issue one 128-k chunk's staging (hi+lo planes) via cp.async; 8 x 16B per thread
#define STAGE_CHUNK_ASYNC(shi_, slo_, cbuf, chunk) do {                        \
    u32 _hb = smb + SM_H + (cbuf) * 2 * HPLANE;                                 \
    _Pragma("unroll")                                                           \
    for (int _q = 0; _q < 4; _q++) {                                            \
        int _idx = _q * 256 + tid;                                              \
        int _row = _idx >> 4, _kq = _idx & 15;                                  \
        u32 _d = _hb + _row * (HPIT * 2) + _kq * 16;                            \
        size_t _off = (size_t)_row * HH + (chunk) * 128 + _kq * 8;              \
        CP_ASYNC16(_d, (const char*)((shi_) + _off));                           \
        CP_ASYNC16(_d + HPLANE, (const char*)((slo_) + _off));                  \
    }                                                                           \
} while (0)

// ---- persistent LSTM layer via mma.sync ----
__global__ __launch_bounds__(256) void lstm_layer_tc(const float* __restrict__ Whh, int layer)
{
    extern __shared__ char smem[];
    const u32 smb  = (u32)__cvta_generic_to_shared(smem);
    const int tid  = threadIdx.x;
    const int cb   = blockIdx.x;
    const int wid  = tid >> 5;
    const int lane = tid & 31;
    const int g8   = lane >> 2;
    const int tg   = lane & 3;
    const int bh   = wid & 1;
    const int ks   = wid >> 1;

    // one-time: stage split W slice
    {
        u16* whi = (u16*)(smem + SM_WHI);
        u16* wlo = (u16*)(smem + SM_WLO);
        for (int i = tid; i < 32 * HH; i += 256) {
            int n = i >> 10, k = i & 1023;
            int j = (n >> 3) * HH + cb * 8 + (n & 7);
            float w = Whh[(size_t)j * HH + k];
            __nv_bfloat16 h16 = __float2bfloat16(w);
            __nv_bfloat16 l16 = __float2bfloat16(w - __bfloat162float(h16));
            whi[n * WPIT + k] = *(u16*)&h16;
            wlo[n * WPIT + k] = *(u16*)&l16;
        }
    }
    __syncthreads();

    float cs[2][4];
    #pragma unroll
    for (int rb = 0; rb < 2; rb++)
        #pragma unroll
        for (int q = 0; q < 4; q++) cs[rb][q] = 0.0f;

    float* sXG = (float*)(smem + SM_XG);
    const int xr0 = tid >> 4,         xs0 = tid & 15;
    const int xr1 = (256 + tid) >> 4, xs1 = tid & 15;

    for (int t = 0; t < TT; t++) {
        const float* xg = g_xg + (size_t)t * G4 * BB;
        float4 xga = __ldcg((const float4*)(xg
                        + (size_t)((xr0 >> 3) * HH + cb * 8 + (xr0 & 7)) * BB + xs0 * 4));
        float4 xgb = __ldcg((const float4*)(xg
                        + (size_t)((xr1 >> 3) * HH + cb * 8 + (xr1 & 7)) * BB + xs1 * 4));

        float acc[2][4][4];
        #pragma unroll
        for (int rb = 0; rb < 2; rb++)
            #pragma unroll
            for (int nt = 0; nt < 4; nt++)
                #pragma unroll
                for (int q = 0; q < 4; q++) acc[rb][nt][q] = 0.0f;

        if (t > 0) {
            const __nv_bfloat16* shi = g_hhi[(t - 1) & 1];
            const __nv_bfloat16* slo = g_hlo[(t - 1) & 1];

            STAGE_CHUNK_ASYNC(shi, slo, 0, 0);
            CP_COMMIT();

            for (int c = 0; c < 8; c++) {
                CP_WAIT0();
                __syncthreads();                 // chunk c visible; mma(c-1) done by all
                if (c < 7) {
                    STAGE_CHUNK_ASYNC(shi, slo, (c + 1) & 1, c + 1);
                    CP_COMMIT();
                }

                char* hbuf = smem + SM_H + (c & 1) * 2 * HPLANE;
                const u16* hhi = (const u16*)hbuf;
                const u16* hlo = (const u16*)(hbuf + HPLANE);
                const u16* whi = (const u16*)(smem + SM_WHI);
                const u16* wlo = (const u16*)(smem + SM_WLO);

                #pragma unroll
                for (int kst = 0; kst < 2; kst++) {
                    const int kk = ks * 32 + kst * 16;
                    const int kg = c * 128 + kk;
                    u32 Ahi[2][4], Alo[2][4], Bhi[4][2], Blo[4][2];
                    #pragma unroll
                    for (int rb = 0; rb < 2; rb++) {
                        const u16* p = hhi + (bh * 32 + rb * 16 + g8) * HPIT + kk + tg * 2;
                        Ahi[rb][0] = *(const u32*)p;
                        Ahi[rb][1] = *(const u32*)(p + 8 * HPIT);
                        Ahi[rb][2] = *(const u32*)(p + 8);
                        Ahi[rb][3] = *(const u32*)(p + 8 * HPIT + 8);
                        const u16* pl = hlo + (bh * 32 + rb * 16 + g8) * HPIT + kk + tg * 2;
                        Alo[rb][0] = *(const u32*)pl;
                        Alo[rb][1] = *(const u32*)(pl + 8 * HPIT);
                        Alo[rb][2] = *(const u32*)(pl + 8);
                        Alo[rb][3] = *(const u32*)(pl + 8 * HPIT + 8);
                    }
                    #pragma unroll
                    for (int nt = 0; nt < 4; nt++) {
                        const u16* p = whi + (nt * 8 + g8) * WPIT + kg + tg * 2;
                        Bhi[nt][0] = *(const u32*)p;
                        Bhi[nt][1] = *(const u32*)(p + 8);
                        const u16* pl = wlo + (nt * 8 + g8) * WPIT + kg + tg * 2;
                        Blo[nt][0] = *(const u32*)pl;
                        Blo[nt][1] = *(const u32*)(pl + 8);
                    }
                    #pragma unroll
                    for (int rb = 0; rb < 2; rb++)
                        #pragma unroll
                        for (int nt = 0; nt < 4; nt++) {
                            mma16816(acc[rb][nt], Ahi[rb], Bhi[nt]);
                            mma16816(acc[rb][nt], Ahi[rb], Blo[nt]);
                            mma16816(acc[rb][nt], Alo[rb], Bhi[nt]);
                        }
                }
            }
        }

        // publish xg + reduction writes (disjoint smem regions), then ONE sync
        *(float4*)(sXG + xr0 * 68 + xs0 * 4) = xga;
        *(float4*)(sXG + xr1 * 68 + xs1 * 4) = xgb;
        if (t > 0) {
            float* red = (float*)(smem + SM_H);   // overlays buf0; chunk 7 used buf1
            if (ks > 0) {
                int s = (ks - 1) * 2 + bh;
                #pragma unroll
                for (int rb = 0; rb < 2; rb++)
                    #pragma unroll
                    for (int nt = 0; nt < 4; nt++)
                        #pragma unroll
                        for (int q = 0; q < 4; q++)
                            red[(size_t)s * (32 * 33) + (rb * 16 + nt * 4 + q) * 33 + lane]
                                = acc[rb][nt][q];
            }
        }
        __syncthreads();
        if (t > 0 && ks == 0) {
            float* red = (float*)(smem + SM_H);
            #pragma unroll
            for (int s = 0; s < 3; s++)
                #pragma unroll
                for (int rb = 0; rb < 2; rb++)
                    #pragma unroll
                    for (int nt = 0; nt < 4; nt++)
                        #pragma unroll
                        for (int q = 0; q < 4; q++)
                            acc[rb][nt][q] +=
                                red[(size_t)(s * 2 + bh) * (32 * 33)
                                    + (rb * 16 + nt * 4 + q) * 33 + lane];
        }

        // ---- epilogue: warps 0-1; gates lane-local; xg from smem ----
        if (wid < 2) {
            #pragma unroll
            for (int rb = 0; rb < 2; rb++) {
                #pragma unroll
                for (int q = 0; q < 4; q++) {
                    int b  = bh * 32 + rb * 16 + g8 + ((q >> 1) ? 8 : 0);
                    int cc = tg * 2 + (q & 1);
                    int jb = cb * 8 + cc;
                    float gi = acc[rb][0][q] + sXG[(0  + cc) * 68 + b];
                    float gf = acc[rb][1][q] + sXG[(8  + cc) * 68 + b];
                    float gg = acc[rb][2][q] + sXG[(16 + cc) * 68 + b];
                    float go = acc[rb][3][q] + sXG[(24 + cc) * 68 + b];
                    float cnew = sigm(gf) * cs[rb][q] + sigm(gi) * tanhf(gg);
                    float hnew = sigm(go) * tanhf(cnew);
                    cs[rb][q] = cnew;
                    __nv_bfloat16 h16 = __float2bfloat16(hnew);
                    __nv_bfloat16 l16 = __float2bfloat16(hnew - __bfloat162float(h16));
                    if (layer == 0) {
                        g_h1hi[(size_t)t * BB * HH + (size_t)b * HH + jb] = h16;
                        g_h1lo[(size_t)t * BB * HH + (size_t)b * HH + jb] = l16;
                    } else if (t == TT - 1) {
                        g_h2[(size_t)jb * BB + b] = hnew;
                    }
                    g_hhi[t & 1][(size_t)b * HH + jb] = h16;
                    g_hlo[t & 1][(size_t)b * HH + jb] = l16;
                }
            }
            __threadfence();                     // writer warps only
        }

        // ---- global barrier ----
        if (t < TT - 1) {
            __syncthreads();
            if (tid == 0) {
                atomicAdd(&g_bar[t], 1);
                while (*(volatile int*)(g_bar + t) < NCTA) { }
            }
            __syncthreads();
        }
    }
}

// ---- xg1 = h1 @ Wih1^T + bias : clone of the recurrence matmul ----
__global__ __launch_bounds__(256) void xg1_tc(
    const float* __restrict__ Wih,
    const float* __restrict__ bih, const float* __restrict__ bhh)
{
    extern __shared__ char smem[];
    const u32 smb  = (u32)__cvta_generic_to_shared(smem);
    const int tid  = threadIdx.x;
    const int cb   = blockIdx.x;
    const int wid  = tid >> 5;
    const int lane = tid & 31;
    const int g8   = lane >> 2;
    const int tg   = lane & 3;
    const int bh   = wid & 1;
    const int ks   = wid >> 1;

    // stage split W slice
    {
        u16* whi = (u16*)(smem + SM_WHI);
        u16* wlo = (u16*)(smem + SM_WLO);
        for (int i = tid; i < 32 * HH; i += 256) {
            int n = i >> 10, k = i & 1023;
            int j = (n >> 3) * HH + cb * 8 + (n & 7);
            float w = Wih[(size_t)j * HH + k];
            __nv_bfloat16 h16 = __float2bfloat16(w);
            __nv_bfloat16 l16 = __float2bfloat16(w - __bfloat162float(h16));
            whi[n * WPIT + k] = *(u16*)&h16;
            wlo[n * WPIT + k] = *(u16*)&l16;
        }
    }
    __syncthreads();

    float bias[4][2];
    #pragma unroll
    for (int gate = 0; gate < 4; gate++)
        #pragma unroll
        for (int c01 = 0; c01 < 2; c01++) {
            int j = gate * HH + cb * 8 + tg * 2 + c01;
            bias[gate][c01] = bih[j] + bhh[j];
        }

    const int t0 = blockIdx.y * (TT / 4);
    for (int t = t0; t < t0 + TT / 4; t++) {
        const __nv_bfloat16* shi = g_h1hi + (size_t)t * BB * HH;
        const __nv_bfloat16* slo = g_h1lo + (size_t)t * BB * HH;

        float acc[2][4][4];
        #pragma unroll
        for (int rb = 0; rb < 2; rb++)
            #pragma unroll
            for (int nt = 0; nt < 4; nt++)
                #pragma unroll
                for (int q = 0; q < 4; q++) acc[rb][nt][q] = 0.0f;

        STAGE_CHUNK_ASYNC(shi, slo, 0, 0);
        CP_COMMIT();

        for (int c = 0; c < 8; c++) {
            CP_WAIT0();
            __syncthreads();
            if (c < 7) {
                STAGE_CHUNK_ASYNC(shi, slo, (c + 1) & 1, c + 1);
                CP_COMMIT();
            }

            char* hbuf = smem + SM_H + (c & 1) * 2 * HPLANE;
            const u16* hhi = (const u16*)hbuf;
            const u16* hlo = (const u16*)(hbuf + HPLANE);
            const u16* whi = (const u16*)(smem + SM_WHI);
            const u16* wlo = (const u16*)(smem + SM_WLO);

            #pragma unroll
            for (int kst = 0; kst < 2; kst++) {
                const int kk = ks * 32 + kst * 16;
                const int kg = c * 128 + kk;
                u32 Ahi[2][4], Alo[2][4], Bhi[4][2], Blo[4][2];
                #pragma unroll
                for (int rb = 0; rb < 2; rb++) {
                    const u16* p = hhi + (bh * 32 + rb * 16 + g8) * HPIT + kk + tg * 2;
                    Ahi[rb][0] = *(const u32*)p;
                    Ahi[rb][1] = *(const u32*)(p + 8 * HPIT);
                    Ahi[rb][2] = *(const u32*)(p + 8);
                    Ahi[rb][3] = *(const u32*)(p + 8 * HPIT + 8);
                    const u16* pl = hlo + (bh * 32 + rb * 16 + g8) * HPIT + kk + tg * 2;
                    Alo[rb][0] = *(const u32*)pl;
                    Alo[rb][1] = *(const u32*)(pl + 8 * HPIT);
                    Alo[rb][2] = *(const u32*)(pl + 8);
                    Alo[rb][3] = *(const u32*)(pl + 8 * HPIT + 8);
                }
                #pragma unroll
                for (int nt = 0; nt < 4; nt++) {
                    const u16* p = whi + (nt * 8 + g8) * WPIT + kg + tg * 2;
                    Bhi[nt][0] = *(const u32*)p;
                    Bhi[nt][1] = *(const u32*)(p + 8);
                    const u16* pl = wlo + (nt * 8 + g8) * WPIT + kg + tg * 2;
                    Blo[nt][0] = *(const u32*)pl;
                    Blo[nt][1] = *(const u32*)(pl + 8);
                }
                #pragma unroll
                for (int rb = 0; rb < 2; rb++)
                    #pragma unroll
                    for (int nt = 0; nt < 4; nt++) {
                        mma16816(acc[rb][nt], Ahi[rb], Bhi[nt]);
                        mma16816(acc[rb][nt], Ahi[rb], Blo[nt]);
                        mma16816(acc[rb][nt], Alo[rb], Bhi[nt]);
                    }
            }
        }

        // single-round 4-way k-split reduction
        {
            float* red = (float*)(smem + SM_H);
            if (ks > 0) {
                int s = (ks - 1) * 2 + bh;
                #pragma unroll
                for (int rb = 0; rb < 2; rb++)
                    #pragma unroll
                    for (int nt = 0; nt < 4; nt++)
                        #pragma unroll
                        for (int q = 0; q < 4; q++)
                            red[(size_t)s * (32 * 33) + (rb * 16 + nt * 4 + q) * 33 + lane]
                                = acc[rb][nt][q];
            }
            __syncthreads();
            if (ks == 0) {
                #pragma unroll
                for (int s = 0; s < 3; s++)
                    #pragma unroll
                    for (int rb = 0; rb < 2; rb++)
                        #pragma unroll
                        for (int nt = 0; nt < 4; nt++)
                            #pragma unroll
                            for (int q = 0; q < 4; q++)
                                acc[rb][nt][q] +=
                                    red[(size_t)(s * 2 + bh) * (32 * 33)
                                        + (rb * 16 + nt * 4 + q) * 33 + lane];
            }
        }

        // epilogue: warps 0-1 write xg[t]
        if (wid < 2) {
            float* xgw = g_xg + (size_t)t * G4 * BB;
            #pragma unroll
            for (int rb = 0; rb < 2; rb++) {
                #pragma unroll
                for (int q = 0; q < 4; q++) {
                    int b  = bh * 32 + rb * 16 + g8 + ((q >> 1) ? 8 : 0);
                    int cc = tg * 2 + (q & 1);
                    int jb = cb * 8 + cc;
                    #pragma unroll
                    for (int gate = 0; gate < 4; gate++)
                        xgw[(size_t)(gate * HH + jb) * BB + b]
                            = acc[rb][gate][q] + bias[gate][q & 1];
                }
            }
        }
        // order reduction-slot reads before next iteration's chunk-0 staging
        __syncthreads();
    }
}

// ---- head ----
__global__ __launch_bounds__(128) void head_kernel(
    const float* __restrict__ Wh, const float* __restrict__ bh, float* __restrict__ out)
{
    __shared__ float red[4];
    const int r = blockIdx.x, b = blockIdx.y;
    const int tid = threadIdx.x;

    float s = 0.0f;
    for (int k = tid; k < HH; k += 128) s += g_h2[(size_t)k * BB + b] * Wh[(size_t)r * HH + k];
    #pragma unroll
    for (int o = 16; o > 0; o >>= 1) s += __shfl_down_sync(0xFFFFFFFFu, s, o);
    if ((tid & 31) == 0) red[tid >> 5] = s;
    __syncthreads();
    if (tid == 0) out[b * HOR + r] = red[0] + red[1] + red[2] + red[3] + bh[r];
}

extern "C" void kernel_launch(void* const* d_in, const int* in_sizes, int n_in,
                              void* d_out, int out_size) {
    const float* x     = (const float*)d_in[0];
    const float* Wih0  = (const float*)d_in[1];
    const float* Whh0  = (const float*)d_in[2];
    const float* bih0  = (const float*)d_in[3];
    const float* bhh0  = (const float*)d_in[4];
    const float* Wih1  = (const float*)d_in[5];
    const float* Whh1  = (const float*)d_in[6];
    const float* bih1  = (const float*)d_in[7];
    const float* bhh1  = (const float*)d_in[8];
    const float* Whead = (const float*)d_in[9];
    const float* bhead = (const float*)d_in[10];
    float* out = (float*)d_out;

    static int configured = 0;
    if (!configured) {
        cudaFuncSetAttribute(lstm_layer_tc,
                             cudaFuncAttributeMaxDynamicSharedMemorySize, SMEM_TC);
        cudaFuncSetAttribute(xg1_tc,
                             cudaFuncAttributeMaxDynamicSharedMemorySize, SMEM_TC);
        configured = 1;
    }

    // layer 0
    zero_state<<<2, 256>>>();
    gemm0<<<dim3(G4 / 128, TT), 128>>>(x, Wih0, bih0, bhh0);
    lstm_layer_tc<<<NCTA, 256, SMEM_TC>>>(Whh0, 0);    // writes g_h1hi/lo history

    // layer 1
    xg1_tc<<<dim3(NCTA, 4), 256, SMEM_TC>>>(Wih1, bih1, bhh1);
    zero_state<<<2, 256>>>();
    lstm_layer_tc<<<NCTA, 256, SMEM_TC>>>(Whh1, 1);

    // head
    head_kernel<<<dim3(HOR, BB), 128>>>(Whead, bhead, out);
}

// round 16
// speedup vs baseline: 1.1048x; 1.1048x over previous
#include <cuda_runtime.h>
#include <cuda_bf16.h>
#include <cstdint>

#define BB   64
#define TT   512
#define II   256
#define HH   1024
#define G4   4096
#define HOR  24
#define NCTA 128

typedef unsigned long long u64;
typedef uint32_t u32;
typedef uint16_t u16;

// ---- scratch (device globals; allocation-free) ----
__device__ float g_xg[(size_t)TT * G4 * BB];           // [T][4H][B]
__device__ float g_h2[HH * BB];                        // layer1 final h [jb][b]
__device__ __nv_bfloat16 g_hhi[2][(size_t)BB * HH];    // ping-pong split h, [b][k]
__device__ __nv_bfloat16 g_hlo[2][(size_t)BB * HH];
__device__ __nv_bfloat16 g_h1hi[(size_t)TT * BB * HH]; // layer0 h history split hi, [t][b][k]
__device__ __nv_bfloat16 g_h1lo[(size_t)TT * BB * HH]; // layer0 h history split lo
__device__ int g_bar[TT];

// ---- scalar helpers ----
__device__ __forceinline__ u64 pack2(float lo, float hi) {
    u64 r; asm("mov.b64 %0, {%1, %2};" : "=l"(r) : "f"(lo), "f"(hi)); return r;
}
__device__ __forceinline__ void fma2(u64& d, u64 a, u64 b) {
    asm("fma.rn.f32x2 %0, %1, %2, %0;" : "+l"(d) : "l"(a), "l"(b));
}
__device__ __forceinline__ float sigm(float x) { return 1.0f / (1.0f + __expf(-x)); }

// m16n8k16 bf16 mma, accumulate in place
__device__ __forceinline__ void mma16816(float* d, const u32* a, const u32* b) {
    asm volatile(
        "mma.sync.aligned.m16n8k16.row.col.f32.bf16.bf16.f32 "
        "{%0,%1,%2,%3}, {%4,%5,%6,%7}, {%8,%9}, {%0,%1,%2,%3};\n"
        : "+f"(d[0]), "+f"(d[1]), "+f"(d[2]), "+f"(d[3])
        : "r"(a[0]), "r"(a[1]), "r"(a[2]), "r"(a[3]), "r"(b[0]), "r"(b[1]));
}

// ldmatrix x4: lanes {0-7,8-15,16-23,24-31} supply row addrs of 4 8x8 b16 tiles -> r0..r3
__device__ __forceinline__ void ldsm4(u32& r0, u32& r1, u32& r2, u32& r3, u32 addr) {
    asm volatile("ldmatrix.sync.aligned.m8n8.x4.shared.b16 {%0,%1,%2,%3}, [%4];"
        : "=r"(r0), "=r"(r1), "=r"(r2), "=r"(r3) : "r"(addr));
}

// ---- zero barrier counters ----
__global__ void zero_state() {
    int i = blockIdx.x * blockDim.x + threadIdx.x;
    if (i < TT) g_bar[i] = 0;
}

// ---- layer-0 input projection GEMM (fp32 FFMA2, proven; K=II) ----
__global__ __launch_bounds__(128) void gemm0(
    const float* __restrict__ X, const float* __restrict__ W,
    const float* __restrict__ bih, const float* __restrict__ bhh)
{
    __shared__ __align__(16) float sA[16 * 68];
    __shared__ __align__(16) float sWt[16 * 132];
    __shared__ float sBias[128];

    const int tid = threadIdx.x;
    const int t   = blockIdx.y;
    const int j0  = blockIdx.x * 128;
    const int jg  = tid & 15;
    const int bg  = tid >> 4;

    sBias[tid] = bih[j0 + tid] + bhh[j0 + tid];
    __syncthreads();

    u64 acc[32];
    #pragma unroll
    for (int jl = 0; jl < 8; jl++) {
        float bj = sBias[jg * 8 + jl];
        u64 p = pack2(bj, bj);
        acc[jl * 4 + 0] = p; acc[jl * 4 + 1] = p;
        acc[jl * 4 + 2] = p; acc[jl * 4 + 3] = p;
    }

    for (int k0 = 0; k0 < II; k0 += 16) {
        __syncthreads();
        #pragma unroll
        for (int q = 0; q < 2; q++) {
            int f = q * 128 + tid;
            int b = f >> 2, kq = f & 3;
            float4 v = *(const float4*)(X + ((size_t)b * TT + t) * II + k0 + kq * 4);
            sA[(kq * 4 + 0) * 68 + b] = v.x;
            sA[(kq * 4 + 1) * 68 + b] = v.y;
            sA[(kq * 4 + 2) * 68 + b] = v.z;
            sA[(kq * 4 + 3) * 68 + b] = v.w;
        }
        #pragma unroll
        for (int q = 0; q < 4; q++) {
            int f = q * 128 + tid;
            int j = f >> 2, kq = f & 3;
            float4 v = *(const float4*)(W + (size_t)(j0 + j) * II + k0 + kq * 4);
            sWt[(kq * 4 + 0) * 132 + j] = v.x;
            sWt[(kq * 4 + 1) * 132 + j] = v.y;
            sWt[(kq * 4 + 2) * 132 + j] = v.z;
            sWt[(kq * 4 + 3) * 132 + j] = v.w;
        }
        __syncthreads();
        #pragma unroll
        for (int kk = 0; kk < 16; kk++) {
            longlong2 ha = *(const longlong2*)(sA + kk * 68 + bg * 8);
            longlong2 hb = *(const longlong2*)(sA + kk * 68 + bg * 8 + 4);
            float4 w0 = *(const float4*)(sWt + kk * 132 + jg * 8);
            float4 w1 = *(const float4*)(sWt + kk * 132 + jg * 8 + 4);
            u64 hq[4] = { (u64)ha.x, (u64)ha.y, (u64)hb.x, (u64)hb.y };
            u64 p[8]  = { pack2(w0.x, w0.x), pack2(w0.y, w0.y),
                          pack2(w0.z, w0.z), pack2(w0.w, w0.w),
                          pack2(w1.x, w1.x), pack2(w1.y, w1.y),
                          pack2(w1.z, w1.z), pack2(w1.w, w1.w) };
            #pragma unroll
            for (int jl = 0; jl < 8; jl++)
                #pragma unroll
                for (int bp = 0; bp < 4; bp++)
                    fma2(acc[jl * 4 + bp], hq[bp], p[jl]);
        }
    }
    #pragma unroll
    for (int jl = 0; jl < 8; jl++) {
        float* orow = g_xg + ((size_t)t * G4 + j0 + jg * 8 + jl) * BB + bg * 8;
        *(u64*)(orow + 0) = acc[jl * 4 + 0];
        *(u64*)(orow + 2) = acc[jl * 4 + 1];
        *(u64*)(orow + 4) = acc[jl * 4 + 2];
        *(u64*)(orow + 6) = acc[jl * 4 + 3];
    }
}

// ---- smem layout shared by recurrence + xg1 kernels ----
#define WPIT   1032
#define HPIT   136
#define SM_WHI 0
#define SM_WLO (32 * WPIT * 2)                 // 66048
#define SM_H   (SM_WLO + 32 * WPIT * 2)        // 132096
#define HPLANE (64 * HPIT * 2)                 // 17408
#define SM_XG  (SM_H + 4 * HPLANE)             // 201728; 32x68 f32 = 8704
#define SMEM_TC (SM_XG + 32 * 68 * 4)          // 210432

// ---- persistent LSTM layer via mma.sync (R14 base + ldmatrix fragments) ----
__global__ __launch_bounds__(256) void lstm_layer_tc(const float* __restrict__ Whh, int layer)
{
    extern __shared__ char smem[];
    const u32 smb  = (u32)__cvta_generic_to_shared(smem);
    const int tid  = threadIdx.x;
    const int cb   = blockIdx.x;
    const int wid  = tid >> 5;
    const int lane = tid & 31;
    const int g8   = lane >> 2;
    const int tg   = lane & 3;
    const int bh   = wid & 1;
    const int ks   = wid >> 1;

    // ldmatrix lane->row mapping constants
    const int l8    = lane & 7, lt = lane >> 3;
    const int arow0 = bh * 32 + ((lt & 1) << 3) + l8;   // + rb*16 per use
    const int akoff = (lt >> 1) << 3;                   // u16 elems
    const int brow0 = ((lt >> 1) << 3) + l8;            // + ntp*16 per use
    const int bkoff = (lt & 1) << 3;

    // one-time: stage split W slice
    {
        u16* whi = (u16*)(smem + SM_WHI);
        u16* wlo = (u16*)(smem + SM_WLO);
        for (int i = tid; i < 32 * HH; i += 256) {
            int n = i >> 10, k = i & 1023;
            int j = (n >> 3) * HH + cb * 8 + (n & 7);
            float w = Whh[(size_t)j * HH + k];
            __nv_bfloat16 h16 = __float2bfloat16(w);
            __nv_bfloat16 l16 = __float2bfloat16(w - __bfloat162float(h16));
            whi[n * WPIT + k] = *(u16*)&h16;
            wlo[n * WPIT + k] = *(u16*)&l16;
        }
    }
    __syncthreads();

    float cs[2][4];
    #pragma unroll
    for (int rb = 0; rb < 2; rb++)
        #pragma unroll
        for (int q = 0; q < 4; q++) cs[rb][q] = 0.0f;

    float* sXG = (float*)(smem + SM_XG);
    const int xr0 = tid >> 4,         xs0 = tid & 15;
    const int xr1 = (256 + tid) >> 4, xs1 = tid & 15;

    for (int t = 0; t < TT; t++) {
        const float* xg = g_xg + (size_t)t * G4 * BB;
        float4 xga = __ldcg((const float4*)(xg
                        + (size_t)((xr0 >> 3) * HH + cb * 8 + (xr0 & 7)) * BB + xs0 * 4));
        float4 xgb = __ldcg((const float4*)(xg
                        + (size_t)((xr1 >> 3) * HH + cb * 8 + (xr1 & 7)) * BB + xs1 * 4));

        float acc[2][4][4];
        #pragma unroll
        for (int rb = 0; rb < 2; rb++)
            #pragma unroll
            for (int nt = 0; nt < 4; nt++)
                #pragma unroll
                for (int q = 0; q < 4; q++) acc[rb][nt][q] = 0.0f;

        if (t > 0) {
            const __nv_bfloat16* shi = g_hhi[(t - 1) & 1];
            const __nv_bfloat16* slo = g_hlo[(t - 1) & 1];

            uint4 pf[2][4];
            #pragma unroll
            for (int q = 0; q < 4; q++) {
                int idx = q * 256 + tid;
                int row = idx >> 4, kq = idx & 15;
                size_t off = (size_t)row * HH + kq * 8;
                pf[0][q] = __ldcg((const uint4*)(shi + off));
                pf[1][q] = __ldcg((const uint4*)(slo + off));
            }

            for (int c = 0; c < 8; c++) {
                char* hbuf = smem + SM_H + (c & 1) * 2 * HPLANE;
                #pragma unroll
                for (int q = 0; q < 4; q++) {
                    int idx = q * 256 + tid;
                    int row = idx >> 4, kq = idx & 15;
                    *(uint4*)(hbuf + row * (HPIT * 2) + kq * 16) = pf[0][q];
                    *(uint4*)(hbuf + HPLANE + row * (HPIT * 2) + kq * 16) = pf[1][q];
                }
                __syncthreads();

                if (c < 7) {
                    #pragma unroll
                    for (int q = 0; q < 4; q++) {
                        int idx = q * 256 + tid;
                        int row = idx >> 4, kq = idx & 15;
                        size_t off = (size_t)row * HH + (c + 1) * 128 + kq * 8;
                        pf[0][q] = __ldcg((const uint4*)(shi + off));
                        pf[1][q] = __ldcg((const uint4*)(slo + off));
                    }
                }

                const u32 hb0 = smb + SM_H + (c & 1) * 2 * HPLANE;

                #pragma unroll
                for (int kst = 0; kst < 2; kst++) {
                    const int kk = ks * 32 + kst * 16;
                    const int kg = c * 128 + kk;
                    u32 Ahi[2][4], Alo[2][4], Bhi[4][2], Blo[4][2];
                    #pragma unroll
                    for (int rb = 0; rb < 2; rb++) {
                        u32 aoff = (u32)(((arow0 + rb * 16) * HPIT + kk + akoff) * 2);
                        ldsm4(Ahi[rb][0], Ahi[rb][1], Ahi[rb][2], Ahi[rb][3], hb0 + aoff);
                        ldsm4(Alo[rb][0], Alo[rb][1], Alo[rb][2], Alo[rb][3],
                              hb0 + HPLANE + aoff);
                    }
                    #pragma unroll
                    for (int ntp = 0; ntp < 2; ntp++) {
                        u32 boff = (u32)(((brow0 + ntp * 16) * WPIT + kg + bkoff) * 2);
                        ldsm4(Bhi[2 * ntp][0], Bhi[2 * ntp][1],
                              Bhi[2 * ntp + 1][0], Bhi[2 * ntp + 1][1], smb + SM_WHI + boff);
                        ldsm4(Blo[2 * ntp][0], Blo[2 * ntp][1],
                              Blo[2 * ntp + 1][0], Blo[2 * ntp + 1][1], smb + SM_WLO + boff);
                    }
                    #pragma unroll
                    for (int rb = 0; rb < 2; rb++)
                        #pragma unroll
                        for (int nt = 0; nt < 4; nt++) {
                            mma16816(acc[rb][nt], Ahi[rb], Bhi[nt]);
                            mma16816(acc[rb][nt], Ahi[rb], Blo[nt]);
                            mma16816(acc[rb][nt], Alo[rb], Bhi[nt]);
                        }
                }
            }
        }

        // publish xg + reduction writes (disjoint smem regions), then ONE sync
        *(float4*)(sXG + xr0 * 68 + xs0 * 4) = xga;
        *(float4*)(sXG + xr1 * 68 + xs1 * 4) = xgb;
        if (t > 0) {
            float* red = (float*)(smem + SM_H);   // overlays buf0; chunk 7 used buf1
            if (ks > 0) {
                int s = (ks - 1) * 2 + bh;
                #pragma unroll
                for (int rb = 0; rb < 2; rb++)
                    #pragma unroll
                    for (int nt = 0; nt < 4; nt++)
                        #pragma unroll
                        for (int q = 0; q < 4; q++)
                            red[(size_t)s * (32 * 33) + (rb * 16 + nt * 4 + q) * 33 + lane]
                                = acc[rb][nt][q];
            }
        }
        __syncthreads();
        if (t > 0 && ks == 0) {
            float* red = (float*)(smem + SM_H);
            #pragma unroll
            for (int s = 0; s < 3; s++)
                #pragma unroll
                for (int rb = 0; rb < 2; rb++)
                    #pragma unroll
                    for (int nt = 0; nt < 4; nt++)
                        #pragma unroll
                        for (int q = 0; q < 4; q++)
                            acc[rb][nt][q] +=
                                red[(size_t)(s * 2 + bh) * (32 * 33)
                                    + (rb * 16 + nt * 4 + q) * 33 + lane];
        }

        // ---- epilogue: warps 0-1; gates lane-local; xg from smem ----
        if (wid < 2) {
            #pragma unroll
            for (int rb = 0; rb < 2; rb++) {
                #pragma unroll
                for (int q = 0; q < 4; q++) {
                    int b  = bh * 32 + rb * 16 + g8 + ((q >> 1) ? 8 : 0);
                    int cc = tg * 2 + (q & 1);
                    int jb = cb * 8 + cc;
                    float gi = acc[rb][0][q] + sXG[(0  + cc) * 68 + b];
                    float gf = acc[rb][1][q] + sXG[(8  + cc) * 68 + b];
                    float gg = acc[rb][2][q] + sXG[(16 + cc) * 68 + b];
                    float go = acc[rb][3][q] + sXG[(24 + cc) * 68 + b];
                    float cnew = sigm(gf) * cs[rb][q] + sigm(gi) * tanhf(gg);
                    float hnew = sigm(go) * tanhf(cnew);
                    cs[rb][q] = cnew;
                    __nv_bfloat16 h16 = __float2bfloat16(hnew);
                    __nv_bfloat16 l16 = __float2bfloat16(hnew - __bfloat162float(h16));
                    if (layer == 0) {
                        g_h1hi[(size_t)t * BB * HH + (size_t)b * HH + jb] = h16;
                        g_h1lo[(size_t)t * BB * HH + (size_t)b * HH + jb] = l16;
                    } else if (t == TT - 1) {
                        g_h2[(size_t)jb * BB + b] = hnew;
                    }
                    g_hhi[t & 1][(size_t)b * HH + jb] = h16;
                    g_hlo[t & 1][(size_t)b * HH + jb] = l16;
                }
            }
            __threadfence();                     // writer warps only
        }

        // ---- global barrier ----
        if (t < TT - 1) {
            __syncthreads();
            if (tid == 0) {
                atomicAdd(&g_bar[t], 1);
                while (*(volatile int*)(g_bar + t) < NCTA) { }
            }
            __syncthreads();
        }
    }
}

// ---- xg1 = h1 @ Wih1^T + bias : clone of the recurrence matmul (ldmatrix variant) ----
__global__ __launch_bounds__(256) void xg1_tc(
    const float* __restrict__ Wih,
    const float* __restrict__ bih, const float* __restrict__ bhh)
{
    extern __shared__ char smem[];
    const u32 smb  = (u32)__cvta_generic_to_shared(smem);
    const int tid  = threadIdx.x;
    const int cb   = blockIdx.x;
    const int wid  = tid >> 5;
    const int lane = tid & 31;
    const int g8   = lane >> 2;
    const int tg   = lane & 3;
    const int bh   = wid & 1;
    const int ks   = wid >> 1;

    const int l8    = lane & 7, lt = lane >> 3;
    const int arow0 = bh * 32 + ((lt & 1) << 3) + l8;
    const int akoff = (lt >> 1) << 3;
    const int brow0 = ((lt >> 1) << 3) + l8;
    const int bkoff = (lt & 1) << 3;

    // stage split W slice
    {
        u16* whi = (u16*)(smem + SM_WHI);
        u16* wlo = (u16*)(smem + SM_WLO);
        for (int i = tid; i < 32 * HH; i += 256) {
            int n = i >> 10, k = i & 1023;
            int j = (n >> 3) * HH + cb * 8 + (n & 7);
            float w = Wih[(size_t)j * HH + k];
            __nv_bfloat16 h16 = __float2bfloat16(w);
            __nv_bfloat16 l16 = __float2bfloat16(w - __bfloat162float(h16));
            whi[n * WPIT + k] = *(u16*)&h16;
            wlo[n * WPIT + k] = *(u16*)&l16;
        }
    }
    __syncthreads();

    float bias[4][2];
    #pragma unroll
    for (int gate = 0; gate < 4; gate++)
        #pragma unroll
        for (int c01 = 0; c01 < 2; c01++) {
            int j = gate * HH + cb * 8 + tg * 2 + c01;
            bias[gate][c01] = bih[j] + bhh[j];
        }

    const int t0 = blockIdx.y * (TT / 4);
    for (int t = t0; t < t0 + TT / 4; t++) {
        const __nv_bfloat16* shi = g_h1hi + (size_t)t * BB * HH;
        const __nv_bfloat16* slo = g_h1lo + (size_t)t * BB * HH;

        float acc[2][4][4];
        #pragma unroll
        for (int rb = 0; rb < 2; rb++)
            #pragma unroll
            for (int nt = 0; nt < 4; nt++)
                #pragma unroll
                for (int q = 0; q < 4; q++) acc[rb][nt][q] = 0.0f;

        uint4 pf[2][4];
        #pragma unroll
        for (int q = 0; q < 4; q++) {
            int idx = q * 256 + tid;
            int row = idx >> 4, kq = idx & 15;
            size_t off = (size_t)row * HH + kq * 8;
            pf[0][q] = __ldcg((const uint4*)(shi + off));
            pf[1][q] = __ldcg((const uint4*)(slo + off));
        }

        for (int c = 0; c < 8; c++) {
            char* hbuf = smem + SM_H + (c & 1) * 2 * HPLANE;
            #pragma unroll
            for (int q = 0; q < 4; q++) {
                int idx = q * 256 + tid;
                int row = idx >> 4, kq = idx & 15;
                *(uint4*)(hbuf + row * (HPIT * 2) + kq * 16) = pf[0][q];
                *(uint4*)(hbuf + HPLANE + row * (HPIT * 2) + kq * 16) = pf[1][q];
            }
            __syncthreads();

            if (c < 7) {
                #pragma unroll
                for (int q = 0; q < 4; q++) {
                    int idx = q * 256 + tid;
                    int row = idx >> 4, kq = idx & 15;
                    size_t off = (size_t)row * HH + (c + 1) * 128 + kq * 8;
                    pf[0][q] = __ldcg((const uint4*)(shi + off));
                    pf[1][q] = __ldcg((const uint4*)(slo + off));
                }
            }

            const u32 hb0 = smb + SM_H + (c & 1) * 2 * HPLANE;

            #pragma unroll
            for (int kst = 0; kst < 2; kst++) {
                const int kk = ks * 32 + kst * 16;
                const int kg = c * 128 + kk;
                u32 Ahi[2][4], Alo[2][4], Bhi[4][2], Blo[4][2];
                #pragma unroll
                for (int rb = 0; rb < 2; rb++) {
                    u32 aoff = (u32)(((arow0 + rb * 16) * HPIT + kk + akoff) * 2);
                    ldsm4(Ahi[rb][0], Ahi[rb][1], Ahi[rb][2], Ahi[rb][3], hb0 + aoff);
                    ldsm4(Alo[rb][0], Alo[rb][1], Alo[rb][2], Alo[rb][3],
                          hb0 + HPLANE + aoff);
                }
                #pragma unroll
                for (int ntp = 0; ntp < 2; ntp++) {
                    u32 boff = (u32)(((brow0 + ntp * 16) * WPIT + kg + bkoff) * 2);
                    ldsm4(Bhi[2 * ntp][0], Bhi[2 * ntp][1],
                          Bhi[2 * ntp + 1][0], Bhi[2 * ntp + 1][1], smb + SM_WHI + boff);
                    ldsm4(Blo[2 * ntp][0], Blo[2 * ntp][1],
                          Blo[2 * ntp + 1][0], Blo[2 * ntp + 1][1], smb + SM_WLO + boff);
                }
                #pragma unroll
                for (int rb = 0; rb < 2; rb++)
                    #pragma unroll
                    for (int nt = 0; nt < 4; nt++) {
                        mma16816(acc[rb][nt], Ahi[rb], Bhi[nt]);
                        mma16816(acc[rb][nt], Ahi[rb], Blo[nt]);
                        mma16816(acc[rb][nt], Alo[rb], Bhi[nt]);
                    }
            }
        }

        // single-round 4-way k-split reduction
        {
            float* red = (float*)(smem + SM_H);
            if (ks > 0) {
                int s = (ks - 1) * 2 + bh;
                #pragma unroll
                for (int rb = 0; rb < 2; rb++)
                    #pragma unroll
                    for (int nt = 0; nt < 4; nt++)
                        #pragma unroll
                        for (int q = 0; q < 4; q++)
                            red[(size_t)s * (32 * 33) + (rb * 16 + nt * 4 + q) * 33 + lane]
                                = acc[rb][nt][q];
            }
            __syncthreads();
            if (ks == 0) {
                #pragma unroll
                for (int s = 0; s < 3; s++)
                    #pragma unroll
                    for (int rb = 0; rb < 2; rb++)
                        #pragma unroll
                        for (int nt = 0; nt < 4; nt++)
                            #pragma unroll
                            for (int q = 0; q < 4; q++)
                                acc[rb][nt][q] +=
                                    red[(size_t)(s * 2 + bh) * (32 * 33)
                                        + (rb * 16 + nt * 4 + q) * 33 + lane];
            }
        }

        // epilogue: warps 0-1 write xg[t]
        if (wid < 2) {
            float* xgw = g_xg + (size_t)t * G4 * BB;
            #pragma unroll
            for (int rb = 0; rb < 2; rb++) {
                #pragma unroll
                for (int q = 0; q < 4; q++) {
                    int b  = bh * 32 + rb * 16 + g8 + ((q >> 1) ? 8 : 0);
                    int cc = tg * 2 + (q & 1);
                    int jb = cb * 8 + cc;
                    #pragma unroll
                    for (int gate = 0; gate < 4; gate++)
                        xgw[(size_t)(gate * HH + jb) * BB + b]
                            = acc[rb][gate][q] + bias[gate][q & 1];
                }
            }
        }
        // order reduction-slot reads before next iteration's chunk-0 staging
        __syncthreads();
    }
}

// ---- head ----
__global__ __launch_bounds__(128) void head_kernel(
    const float* __restrict__ Wh, const float* __restrict__ bh, float* __restrict__ out)
{
    __shared__ float red[4];
    const int r = blockIdx.x, b = blockIdx.y;
    const int tid = threadIdx.x;

    float s = 0.0f;
    for (int k = tid; k < HH; k += 128) s += g_h2[(size_t)k * BB + b] * Wh[(size_t)r * HH + k];
    #pragma unroll
    for (int o = 16; o > 0; o >>= 1) s += __shfl_down_sync(0xFFFFFFFFu, s, o);
    if ((tid & 31) == 0) red[tid >> 5] = s;
    __syncthreads();
    if (tid == 0) out[b * HOR + r] = red[0] + red[1] + red[2] + red[3] + bh[r];
}

extern "C" void kernel_launch(void* const* d_in, const int* in_sizes, int n_in,
                              void* d_out, int out_size) {
    const float* x     = (const float*)d_in[0];
    const float* Wih0  = (const float*)d_in[1];
    const float* Whh0  = (const float*)d_in[2];
    const float* bih0  = (const float*)d_in[3];
    const float* bhh0  = (const float*)d_in[4];
    const float* Wih1  = (const float*)d_in[5];
    const float* Whh1  = (const float*)d_in[6];
    const float* bih1  = (const float*)d_in[7];
    const float* bhh1  = (const float*)d_in[8];
    const float* Whead = (const float*)d_in[9];
    const float* bhead = (const float*)d_in[10];
    float* out = (float*)d_out;

    static int configured = 0;
    if (!configured) {
        cudaFuncSetAttribute(lstm_layer_tc,
                             cudaFuncAttributeMaxDynamicSharedMemorySize, SMEM_TC);
        cudaFuncSetAttribute(xg1_tc,
                             cudaFuncAttributeMaxDynamicSharedMemorySize, SMEM_TC);
        configured = 1;
    }

    // layer 0
    zero_state<<<2, 256>>>();
    gemm0<<<dim3(G4 / 128, TT), 128>>>(x, Wih0, bih0, bhh0);
    lstm_layer_tc<<<NCTA, 256, SMEM_TC>>>(Whh0, 0);    // writes g_h1hi/lo history

    // layer 1
    xg1_tc<<<dim3(NCTA, 4), 256, SMEM_TC>>>(Wih1, bih1, bhh1);
    zero_state<<<2, 256>>>();
    lstm_layer_tc<<<NCTA, 256, SMEM_TC>>>(Whh1, 1);

    // head
    head_kernel<<<dim3(HOR, BB), 128>>>(Whead, bhead, out);
}